// round 1
// baseline (speedup 1.0000x reference)
#include <cuda_runtime.h>
#include <math.h>

#define N_ENT   50000
#define NREL    200
#define DIM     128
#define NB      4
#define E_EDGES 200000
#define S_SAMP  20000
#define WN      640   /* (NB+1)*DIM : [basis0..basis3 | root] */

// ---------------- scratch (device globals; no runtime allocation) ----------
__device__ float g_Wcat[DIM * WN];                    //  320 KB
__device__ float g_Y[(size_t)N_ENT * WN];             //  128 MB
__device__ float g_AGG[(size_t)N_ENT * DIM];          // 25.6 MB
__device__ float g_CNT[N_ENT];                        //  200 KB
__device__ float g_XA[(size_t)N_ENT * DIM];           // 25.6 MB
__device__ float g_XB[(size_t)N_ENT * DIM];           // 25.6 MB
__device__ float g_relT[NREL * DIM];
__device__ float g_relC[NREL * DIM];

// ---------------- helpers ---------------------------------------------------
__global__ void zerok(float* p, long long n) {
    long long i = (long long)blockIdx.x * blockDim.x + threadIdx.x;
    long long stride = (long long)gridDim.x * blockDim.x;
    for (; i < n; i += stride) p[i] = 0.0f;
}

__global__ void count_k(const int* __restrict__ dst) {
    int i = blockIdx.x * blockDim.x + threadIdx.x;
    if (i < E_EDGES) atomicAdd(&g_CNT[dst[i]], 1.0f);
}

__global__ void gather_x0(const int* __restrict__ entity,
                          const float* __restrict__ ectx) {
    int idx = blockIdx.x * blockDim.x + threadIdx.x;  // N_ENT*DIM
    if (idx >= N_ENT * DIM) return;
    int n = idx >> 7, j = idx & 127;
    g_XA[idx] = ectx[(size_t)entity[n] * DIM + j];
}

// Wcat[k, c] : c<512 -> basis[b=c/128][k][c%128] ; c>=512 -> root[k][c-512]
__global__ void build_wcat(const float* __restrict__ basis,
                           const float* __restrict__ root) {
    int idx = blockIdx.x * blockDim.x + threadIdx.x;  // DIM*WN
    if (idx >= DIM * WN) return;
    int k = idx / WN, c = idx % WN;
    float v;
    if (c < NB * DIM) {
        int b = c >> 7, j = c & 127;
        v = basis[((size_t)b * DIM + k) * DIM + j];
    } else {
        v = root[(size_t)k * DIM + (c - NB * DIM)];
    }
    g_Wcat[idx] = v;
}

// ---------------- fp32 SIMT GEMM: C[M,N] = A[M,K] @ B[K,N] ------------------
// BM=BN=64, BK=16, 256 threads, 4x4 microtile. K,N multiples of 16/64; M guarded.
__global__ void gemm64(const float* __restrict__ A, const float* __restrict__ B,
                       float* __restrict__ C, int M, int N, int K) {
    __shared__ float As[16][64];
    __shared__ float Bs[16][64];
    int tid = threadIdx.x;
    int tx = tid & 15;          // N dir
    int ty = tid >> 4;          // M dir
    int m0 = blockIdx.x * 64;
    int n0 = blockIdx.y * 64;

    int arow = tid >> 2, ac4 = tid & 3;     // A tile loader: 64 rows x 4 float4
    int brow = tid >> 4, bc4 = tid & 15;    // B tile loader: 16 rows x 16 float4

    float acc[4][4];
#pragma unroll
    for (int i = 0; i < 4; i++)
#pragma unroll
        for (int j = 0; j < 4; j++) acc[i][j] = 0.0f;

    for (int k0 = 0; k0 < K; k0 += 16) {
        float4 av = make_float4(0.f, 0.f, 0.f, 0.f);
        int gm = m0 + arow;
        if (gm < M)
            av = *(const float4*)(A + (size_t)gm * K + k0 + ac4 * 4);
        As[ac4 * 4 + 0][arow] = av.x;
        As[ac4 * 4 + 1][arow] = av.y;
        As[ac4 * 4 + 2][arow] = av.z;
        As[ac4 * 4 + 3][arow] = av.w;

        *(float4*)(&Bs[brow][bc4 * 4]) =
            *(const float4*)(B + (size_t)(k0 + brow) * N + n0 + bc4 * 4);
        __syncthreads();

#pragma unroll
        for (int k = 0; k < 16; k++) {
            float4 a = *(const float4*)(&As[k][ty * 4]);
            float4 b = *(const float4*)(&Bs[k][tx * 4]);
            acc[0][0] += a.x * b.x; acc[0][1] += a.x * b.y; acc[0][2] += a.x * b.z; acc[0][3] += a.x * b.w;
            acc[1][0] += a.y * b.x; acc[1][1] += a.y * b.y; acc[1][2] += a.y * b.z; acc[1][3] += a.y * b.w;
            acc[2][0] += a.z * b.x; acc[2][1] += a.z * b.y; acc[2][2] += a.z * b.z; acc[2][3] += a.z * b.w;
            acc[3][0] += a.w * b.x; acc[3][1] += a.w * b.y; acc[3][2] += a.w * b.z; acc[3][3] += a.w * b.w;
        }
        __syncthreads();
    }

#pragma unroll
    for (int i = 0; i < 4; i++) {
        int row = m0 + ty * 4 + i;
        if (row < M) {
            float4 v = make_float4(acc[i][0], acc[i][1], acc[i][2], acc[i][3]);
            *(float4*)(C + (size_t)row * N + n0 + tx * 4) = v;
        }
    }
}

// ---------------- edge message scatter --------------------------------------
// warp per edge: msg = norm * sum_b att[type][b] * Y[src, b*128 : b*128+128]
// atomicAdd into AGG[dst].
__global__ void edge_msg(const int* __restrict__ src, const int* __restrict__ dst,
                         const int* __restrict__ etype, const float* __restrict__ enorm,
                         const float* __restrict__ att) {
    int warp = (blockIdx.x * blockDim.x + threadIdx.x) >> 5;
    int lane = threadIdx.x & 31;
    if (warp >= E_EDGES) return;
    int s = src[warp];
    int d = dst[warp];
    int t = etype[warp];
    float nrm = enorm[warp];
    float4 a = *(const float4*)(att + (size_t)t * 4);
    a.x *= nrm; a.y *= nrm; a.z *= nrm; a.w *= nrm;

    const float4* y = (const float4*)(g_Y + (size_t)s * WN);
    float4 y0 = y[lane];
    float4 y1 = y[32 + lane];
    float4 y2 = y[64 + lane];
    float4 y3 = y[96 + lane];

    float4 m;
    m.x = a.x * y0.x + a.y * y1.x + a.z * y2.x + a.w * y3.x;
    m.y = a.x * y0.y + a.y * y1.y + a.z * y2.y + a.w * y3.y;
    m.z = a.x * y0.z + a.y * y1.z + a.z * y2.z + a.w * y3.z;
    m.w = a.x * y0.w + a.y * y1.w + a.z * y2.w + a.w * y3.w;

    float* o = g_AGG + (size_t)d * DIM + lane * 4;
    atomicAdd(o + 0, m.x);
    atomicAdd(o + 1, m.y);
    atomicAdd(o + 2, m.z);
    atomicAdd(o + 3, m.w);
}

// ---------------- per-node finalize: relu(AGG/cnt + Y_root + bias) ----------
__global__ void finalize_k(const float* __restrict__ bias, float* __restrict__ Xout) {
    int idx = blockIdx.x * blockDim.x + threadIdx.x;  // N_ENT*DIM
    if (idx >= N_ENT * DIM) return;
    int n = idx >> 7, j = idx & 127;
    float c = g_CNT[n];
    c = c > 1.0f ? c : 1.0f;
    float v = g_AGG[idx] / c + g_Y[(size_t)n * WN + NB * DIM + j] + bias[j];
    Xout[idx] = v > 0.0f ? v : 0.0f;
}

// ---------------- relation GCN (tiny) ---------------------------------------
__global__ void rel_gemm1(const float* __restrict__ DAD, const float* __restrict__ RC) {
    int idx = blockIdx.x * blockDim.x + threadIdx.x;  // NREL*DIM
    if (idx >= NREL * DIM) return;
    int i = idx >> 7, j = idx & 127;
    float s = 0.0f;
    for (int k = 0; k < NREL; k++) s += DAD[i * NREL + k] * RC[k * DIM + j];
    g_relT[idx] = s;
}

__global__ void rel_gemm2(const float* __restrict__ W) {
    int idx = blockIdx.x * blockDim.x + threadIdx.x;  // NREL*DIM
    if (idx >= NREL * DIM) return;
    int i = idx >> 7, j = idx & 127;
    float s = 0.0f;
    for (int k = 0; k < DIM; k++) s += g_relT[i * DIM + k] * W[k * DIM + j];
    g_relC[idx] = s > 0.0f ? s : 0.0f;
}

// ---------------- gated output gather ---------------------------------------
__global__ void out_kernel(const int* __restrict__ samples,
                           const float* __restrict__ ent_emb,
                           const float* __restrict__ rel_emb,
                           const float* __restrict__ gate_e,
                           const float* __restrict__ gate_r,
                           const float* __restrict__ Xfinal,
                           float* __restrict__ out) {
    int idx = blockIdx.x * blockDim.x + threadIdx.x;  // S_SAMP*DIM
    if (idx >= S_SAMP * DIM) return;
    int s = idx >> 7, j = idx & 127;
    float ge = 1.0f / (1.0f + expf(-gate_e[j]));
    float gr = 1.0f / (1.0f + expf(-gate_r[j]));
    int h = samples[s * 3 + 0];
    int r = samples[s * 3 + 1];
    int t = samples[s * 3 + 2];
    out[idx] = ge * ent_emb[(size_t)h * DIM + j] + (1.0f - ge) * Xfinal[(size_t)h * DIM + j];
    out[(size_t)S_SAMP * DIM + idx] =
        gr * rel_emb[(size_t)r * DIM + j] + (1.0f - gr) * g_relC[(size_t)r * DIM + j];
    out[2 * (size_t)S_SAMP * DIM + idx] =
        ge * ent_emb[(size_t)t * DIM + j] + (1.0f - ge) * Xfinal[(size_t)t * DIM + j];
}

// ---------------- launch -----------------------------------------------------
extern "C" void kernel_launch(void* const* d_in, const int* in_sizes, int n_in,
                              void* d_out, int out_size) {
    const int*   entity  = (const int*)d_in[0];
    const int*   eidx    = (const int*)d_in[1];
    const int*   etype   = (const int*)d_in[2];
    const float* enorm   = (const float*)d_in[3];
    const int*   samples = (const int*)d_in[4];
    const float* DAD     = (const float*)d_in[5];
    const float* ent_emb = (const float*)d_in[6];
    const float* rel_emb = (const float*)d_in[7];
    const float* ectx    = (const float*)d_in[8];
    const float* rctx    = (const float*)d_in[9];
    const float* rgw     = (const float*)d_in[10];
    const float* gate_e  = (const float*)d_in[11];
    const float* gate_r  = (const float*)d_in[12];
    const float* basis1  = (const float*)d_in[13];
    const float* att1    = (const float*)d_in[14];
    const float* root1   = (const float*)d_in[15];
    const float* bias1   = (const float*)d_in[16];
    const float* basis2  = (const float*)d_in[17];
    const float* att2    = (const float*)d_in[18];
    const float* root2   = (const float*)d_in[19];
    const float* bias2   = (const float*)d_in[20];
    float* out = (float*)d_out;

    const int* src = eidx;             // edge_index[0, :]
    const int* dst = eidx + E_EDGES;   // edge_index[1, :]

    float *pW, *pY, *pAGG, *pCNT, *pXA, *pXB;
    cudaGetSymbolAddress((void**)&pW,   g_Wcat);
    cudaGetSymbolAddress((void**)&pY,   g_Y);
    cudaGetSymbolAddress((void**)&pAGG, g_AGG);
    cudaGetSymbolAddress((void**)&pCNT, g_CNT);
    cudaGetSymbolAddress((void**)&pXA,  g_XA);
    cudaGetSymbolAddress((void**)&pXB,  g_XB);

    const int TB = 256;
    const long long ND = (long long)N_ENT * DIM;

    // counts (shared by both layers) + zero accumulators
    zerok<<<2048, TB>>>(pCNT, N_ENT);
    zerok<<<4096, TB>>>(pAGG, ND);
    count_k<<<(E_EDGES + TB - 1) / TB, TB>>>(dst);

    // X0 = entity_context_tab[entity]
    gather_x0<<<(int)((ND + TB - 1) / TB), TB>>>(entity, ectx);

    dim3 ggrid((N_ENT + 63) / 64, WN / 64);

    // ---- layer 1 ----
    build_wcat<<<(DIM * WN + TB - 1) / TB, TB>>>(basis1, root1);
    gemm64<<<ggrid, TB>>>(pXA, pW, pY, N_ENT, WN, DIM);
    edge_msg<<<(E_EDGES * 32 + TB - 1) / TB, TB>>>(src, dst, etype, enorm, att1);
    finalize_k<<<(int)((ND + TB - 1) / TB), TB>>>(bias1, pXB);

    // ---- layer 2 ----
    zerok<<<4096, TB>>>(pAGG, ND);
    build_wcat<<<(DIM * WN + TB - 1) / TB, TB>>>(basis2, root2);
    gemm64<<<ggrid, TB>>>(pXB, pW, pY, N_ENT, WN, DIM);
    edge_msg<<<(E_EDGES * 32 + TB - 1) / TB, TB>>>(src, dst, etype, enorm, att2);
    finalize_k<<<(int)((ND + TB - 1) / TB), TB>>>(bias2, pXA);

    // ---- relation GCN ----
    rel_gemm1<<<(NREL * DIM + TB - 1) / TB, TB>>>(DAD, rctx);
    rel_gemm2<<<(NREL * DIM + TB - 1) / TB, TB>>>(rgw);

    // ---- gated gather ----
    out_kernel<<<(S_SAMP * DIM + TB - 1) / TB, TB>>>(samples, ent_emb, rel_emb,
                                                     gate_e, gate_r, pXA, out);
}